// round 3
// baseline (speedup 1.0000x reference)
#include <cuda_runtime.h>
#include <cuda_bf16.h>
#include <cstdint>

// Problem constants (match reference_code)
#define N_NODES 100000
#define N_EDGES 1000000
#define CH      128        // IN_CH == HID == 128
#define N_CLS   3

// ---------------- scratch (static device globals; no allocation) ------------
// Declared as float4 arrays to guarantee 16-byte alignment for vector ld/st/red.
#define ROW4 (CH / 4)   // 32 float4 per node row
__device__ float4 g_agg[(size_t)N_NODES * ROW4];   // scatter-sum buffer
__device__ float4 g_h1 [(size_t)N_NODES * ROW4];   // layer-1 output
__device__ float4 g_h2 [(size_t)N_NODES * ROW4];   // layer-2 output
__device__ int    g_deg[N_NODES];                  // in-degree (dst counts)

// ---------------- kernels ---------------------------------------------------

// Zero agg (+optionally deg)
__global__ void zero_kernel(float4* __restrict__ agg, int* __restrict__ deg, int zero_deg) {
    size_t total4 = (size_t)N_NODES * ROW4;
    float4 z = make_float4(0.f, 0.f, 0.f, 0.f);
    for (size_t i = (size_t)blockIdx.x * blockDim.x + threadIdx.x; i < total4;
         i += (size_t)gridDim.x * blockDim.x)
        agg[i] = z;
    if (zero_deg) {
        for (int i = blockIdx.x * blockDim.x + threadIdx.x; i < N_NODES;
             i += gridDim.x * blockDim.x)
            deg[i] = 0;
    }
}

// Count destination degrees (once; reused by both layers).
// edge_index is int32, shape [2, E]: row 0 = src, row 1 = dst.
__global__ void deg_kernel(const int* __restrict__ ei, int* __restrict__ deg) {
    int e = blockIdx.x * blockDim.x + threadIdx.x;
    if (e < N_EDGES) {
        int d = __ldg(&ei[N_EDGES + e]);
        atomicAdd(&deg[d], 1);
    }
}

__device__ __forceinline__ void red_add_v4(float4* addr, float4 v) {
    asm volatile("red.global.add.v4.f32 [%0], {%1, %2, %3, %4};"
                 :: "l"(addr), "f"(v.x), "f"(v.y), "f"(v.z), "f"(v.w)
                 : "memory");
}

// One warp per edge: lane l moves float4 l of the 32-float4 node row.
__global__ void scatter_kernel(const int* __restrict__ ei,
                               const float4* __restrict__ feat,
                               float4* __restrict__ agg) {
    int e    = blockIdx.x * 8 + (threadIdx.x >> 5);
    int lane = threadIdx.x & 31;
    int s = __ldg(&ei[e]);
    int d = __ldg(&ei[N_EDGES + e]);
    float4 v = feat[(size_t)s * ROW4 + lane];
    red_add_v4(agg + (size_t)d * ROW4 + lane, v);
}

// Fused dual GEMM + bias + relu:
//   out[r, :] = relu( (agg[r,:]/max(deg[r],1)) @ Wl + b + X[r,:] @ Wr )
// Block: 256 threads, 32 rows x 128 cols tile; thread = 4 rows x 4 cols.
// Wl, Wr (+bias) staged in ~128.5 KB dynamic smem.
__global__ void __launch_bounds__(256)
sage_gemm_kernel(const float4* __restrict__ agg, const int* __restrict__ deg,
                 const float4* __restrict__ X,
                 const float* __restrict__ Wl, const float* __restrict__ bl,
                 const float* __restrict__ Wr, float4* __restrict__ out) {
    extern __shared__ float smem[];
    float* Ws = smem;                 // 128*128
    float* Vs = smem + 16384;         // 128*128
    float* bs = smem + 32768;         // 128

    // stage weights (float4, coalesced)
    {
        const float4* wl4 = reinterpret_cast<const float4*>(Wl);
        const float4* wr4 = reinterpret_cast<const float4*>(Wr);
        float4* ws4 = reinterpret_cast<float4*>(Ws);
        float4* vs4 = reinterpret_cast<float4*>(Vs);
        for (int i = threadIdx.x; i < 4096; i += 256) { ws4[i] = wl4[i]; vs4[i] = wr4[i]; }
        if (threadIdx.x < 32)
            reinterpret_cast<float4*>(bs)[threadIdx.x] =
                reinterpret_cast<const float4*>(bl)[threadIdx.x];
    }
    __syncthreads();

    const int tx = threadIdx.x & 31;     // column group
    const int ty = threadIdx.x >> 5;     // row group (0..7)
    const int row0 = blockIdx.x * 32 + ty * 4;
    const int c0 = tx * 4;

    float inv[4];
    const float4* Ag[4];
    const float4* Xg[4];
#pragma unroll
    for (int i = 0; i < 4; ++i) {
        int r = row0 + i;
        int d = deg[r];
        inv[i] = 1.0f / (float)(d > 0 ? d : 1);
        Ag[i] = agg + (size_t)r * ROW4;
        Xg[i] = X   + (size_t)r * ROW4;
    }

    float accA[4][4] = {};
    float accX[4][4] = {};

#pragma unroll 4
    for (int kg = 0; kg < 32; ++kg) {
        float4 a4[4], x4[4];
#pragma unroll
        for (int i = 0; i < 4; ++i) { a4[i] = Ag[i][kg]; x4[i] = Xg[i][kg]; }
#pragma unroll
        for (int kk = 0; kk < 4; ++kk) {
            int k = kg * 4 + kk;
            float4 w = *reinterpret_cast<const float4*>(Ws + k * CH + c0);
            float4 v = *reinterpret_cast<const float4*>(Vs + k * CH + c0);
#pragma unroll
            for (int i = 0; i < 4; ++i) {
                float aa = reinterpret_cast<const float*>(&a4[i])[kk];
                float xx = reinterpret_cast<const float*>(&x4[i])[kk];
                accA[i][0] = fmaf(aa, w.x, accA[i][0]);
                accA[i][1] = fmaf(aa, w.y, accA[i][1]);
                accA[i][2] = fmaf(aa, w.z, accA[i][2]);
                accA[i][3] = fmaf(aa, w.w, accA[i][3]);
                accX[i][0] = fmaf(xx, v.x, accX[i][0]);
                accX[i][1] = fmaf(xx, v.y, accX[i][1]);
                accX[i][2] = fmaf(xx, v.z, accX[i][2]);
                accX[i][3] = fmaf(xx, v.w, accX[i][3]);
            }
        }
    }

#pragma unroll
    for (int i = 0; i < 4; ++i) {
        float4 o;
        o.x = fmaxf(0.f, fmaf(accA[i][0], inv[i], accX[i][0]) + bs[c0 + 0]);
        o.y = fmaxf(0.f, fmaf(accA[i][1], inv[i], accX[i][1]) + bs[c0 + 1]);
        o.z = fmaxf(0.f, fmaf(accA[i][2], inv[i], accX[i][2]) + bs[c0 + 2]);
        o.w = fmaxf(0.f, fmaf(accA[i][3], inv[i], accX[i][3]) + bs[c0 + 3]);
        out[(size_t)(row0 + i) * ROW4 + tx] = o;
    }
}

// logits = h @ w_cls + b_cls    (thread per node)
__global__ void cls_kernel(const float4* __restrict__ h,
                           const float* __restrict__ wc,
                           const float* __restrict__ bc,
                           float* __restrict__ out) {
    __shared__ float ws[CH * N_CLS];
    __shared__ float bsh[N_CLS];
    for (int i = threadIdx.x; i < CH * N_CLS; i += blockDim.x) ws[i] = wc[i];
    if (threadIdx.x < N_CLS) bsh[threadIdx.x] = bc[threadIdx.x];
    __syncthreads();

    int r = blockIdx.x * blockDim.x + threadIdx.x;
    if (r >= N_NODES) return;

    float a0 = bsh[0], a1 = bsh[1], a2 = bsh[2];
    const float4* row = h + (size_t)r * ROW4;
#pragma unroll 8
    for (int kg = 0; kg < 32; ++kg) {
        float4 hv = row[kg];
#pragma unroll
        for (int kk = 0; kk < 4; ++kk) {
            float hh = reinterpret_cast<const float*>(&hv)[kk];
            int k = kg * 4 + kk;
            a0 = fmaf(hh, ws[k * 3 + 0], a0);
            a1 = fmaf(hh, ws[k * 3 + 1], a1);
            a2 = fmaf(hh, ws[k * 3 + 2], a2);
        }
    }
    out[(size_t)r * 3 + 0] = a0;
    out[(size_t)r * 3 + 1] = a1;
    out[(size_t)r * 3 + 2] = a2;
}

// ---------------- launch -----------------------------------------------------
extern "C" void kernel_launch(void* const* d_in, const int* in_sizes, int n_in,
                              void* d_out, int out_size) {
    const float* x     = (const float*)d_in[0];
    const int*   ei    = (const int*)d_in[1];     // int32 (JAX x64 disabled)
    const float* w_l1  = (const float*)d_in[2];
    const float* b_l1  = (const float*)d_in[3];
    const float* w_r1  = (const float*)d_in[4];
    const float* w_l2  = (const float*)d_in[5];
    const float* b_l2  = (const float*)d_in[6];
    const float* w_r2  = (const float*)d_in[7];
    const float* w_cls = (const float*)d_in[8];
    const float* b_cls = (const float*)d_in[9];
    float*       out   = (float*)d_out;

    float4 *agg, *h1, *h2;
    int* deg;
    cudaGetSymbolAddress((void**)&agg, g_agg);
    cudaGetSymbolAddress((void**)&h1,  g_h1);
    cudaGetSymbolAddress((void**)&h2,  g_h2);
    cudaGetSymbolAddress((void**)&deg, g_deg);

    const float4* x4 = reinterpret_cast<const float4*>(x);

    const int GEMM_SMEM = (16384 + 16384 + 128) * (int)sizeof(float);  // 131584 B
    cudaFuncSetAttribute(sage_gemm_kernel,
                         cudaFuncAttributeMaxDynamicSharedMemorySize, GEMM_SMEM);

    const int ZERO_BLOCKS = 1184;                      // 8 per SM
    const int SCAT_BLOCKS = N_EDGES / 8;               // 1 warp per edge
    const int GEMM_BLOCKS = N_NODES / 32;              // 3125
    const int DEG_BLOCKS  = (N_EDGES + 255) / 256;
    const int CLS_BLOCKS  = (N_NODES + 255) / 256;

    // ---- layer 1 ----
    zero_kernel<<<ZERO_BLOCKS, 256>>>(agg, deg, 1);
    deg_kernel<<<DEG_BLOCKS, 256>>>(ei, deg);
    scatter_kernel<<<SCAT_BLOCKS, 256>>>(ei, x4, agg);
    sage_gemm_kernel<<<GEMM_BLOCKS, 256, GEMM_SMEM>>>(agg, deg, x4, w_l1, b_l1, w_r1, h1);

    // ---- layer 2 ----
    zero_kernel<<<ZERO_BLOCKS, 256>>>(agg, deg, 0);
    scatter_kernel<<<SCAT_BLOCKS, 256>>>(ei, h1, agg);
    sage_gemm_kernel<<<GEMM_BLOCKS, 256, GEMM_SMEM>>>(agg, deg, h1, w_l2, b_l2, w_r2, h2);

    // ---- classifier ----
    cls_kernel<<<CLS_BLOCKS, 256>>>(h2, w_cls, b_cls, out);
}

// round 8
// speedup vs baseline: 1.9590x; 1.9590x over previous
#include <cuda_runtime.h>
#include <cuda_bf16.h>
#include <cstdint>

// Problem constants
#define N_NODES 100000
#define N_EDGES 1000000
#define CH      128
#define N_CLS   3
#define ROW4    (CH / 4)
#define NBLK    ((N_NODES + 127) / 128)   // 782

// B smem layout: [n=128][k=256] bf16, row stride 264 elements (528B) -> 4-bank
// shift per n => conflict-free b-fragment lds.b32
#define BSTRIDE 264
#define BELEMS  (128 * BSTRIDE)           // 33792 elements per matrix

// ---------------- scratch (static device globals; no allocation) ------------
__device__ float4   g_agg[(size_t)N_NODES * ROW4];
__device__ float4   g_h1 [(size_t)N_NODES * ROW4];
__device__ float4   g_h2 [(size_t)N_NODES * ROW4];
__device__ int      g_deg[N_NODES];
__device__ uint16_t g_bhi[2][BELEMS];     // per layer: [n][k] bf16 hi
__device__ uint16_t g_blo[2][BELEMS];     // per layer: [n][k] bf16 lo

// ---------------- simple kernels (known-good) --------------------------------
__global__ void zero_kernel(float4* __restrict__ agg, int* __restrict__ deg, int zero_deg) {
    size_t total4 = (size_t)N_NODES * ROW4;
    float4 z = make_float4(0.f, 0.f, 0.f, 0.f);
    for (size_t i = (size_t)blockIdx.x * blockDim.x + threadIdx.x; i < total4;
         i += (size_t)gridDim.x * blockDim.x)
        agg[i] = z;
    if (zero_deg) {
        for (int i = blockIdx.x * blockDim.x + threadIdx.x; i < N_NODES;
             i += gridDim.x * blockDim.x)
            deg[i] = 0;
    }
}

__global__ void deg_kernel(const int* __restrict__ ei, int* __restrict__ deg) {
    int e = blockIdx.x * blockDim.x + threadIdx.x;
    if (e < N_EDGES) {
        int d = __ldg(&ei[N_EDGES + e]);
        atomicAdd(&deg[d], 1);
    }
}

__device__ __forceinline__ void red_add_v4(float4* addr, float4 v) {
    asm volatile("red.global.add.v4.f32 [%0], {%1, %2, %3, %4};"
                 :: "l"(addr), "f"(v.x), "f"(v.y), "f"(v.z), "f"(v.w) : "memory");
}

__global__ void scatter_kernel(const int* __restrict__ ei,
                               const float4* __restrict__ feat,
                               float4* __restrict__ agg) {
    int e    = blockIdx.x * 8 + (threadIdx.x >> 5);
    int lane = threadIdx.x & 31;
    int s = __ldg(&ei[e]);
    int d = __ldg(&ei[N_EDGES + e]);
    float4 v = feat[(size_t)s * ROW4 + lane];
    red_add_v4(agg + (size_t)d * ROW4 + lane, v);
}

// ---------------- weight prep: transpose + bf16 hi/lo split ------------------
// Conceptual B[k][n], k 0..127 from Wl, 128..255 from Wr (both stored [in][out]).
// Stored at [n * BSTRIDE + k].
__global__ void prep_weights(const float* __restrict__ Wl, const float* __restrict__ Wr,
                             uint16_t* __restrict__ bhi, uint16_t* __restrict__ blo) {
    int idx = blockIdx.x * blockDim.x + threadIdx.x;
    if (idx >= 128 * 256) return;
    int n = idx & 127;
    int k = idx >> 7;
    float w = (k < 128) ? Wl[k * 128 + n] : Wr[(k - 128) * 128 + n];
    __nv_bfloat16 h = __float2bfloat16(w);
    float hf = __bfloat162float(h);
    __nv_bfloat16 l = __float2bfloat16(w - hf);
    int e = n * BSTRIDE + k;
    bhi[e] = *reinterpret_cast<unsigned short*>(&h);
    blo[e] = *reinterpret_cast<unsigned short*>(&l);
}

// ---------------- HMMA dual-GEMM + bias + relu -------------------------------
// out[r,:] = relu( [mean(r) | x(r)] (K=256) @ B + bias ), 3-term bf16 split.
// CTA: 256 threads (8 warps), 128 rows; warp w owns rows [w*16, w*16+16), all 128 cols.
__device__ __forceinline__ uint32_t pack_bf16x2(float lo, float hi) {
    uint32_t r;
    asm("cvt.rn.bf16x2.f32 %0, %1, %2;" : "=r"(r) : "f"(hi), "f"(lo));
    return r;
}
__device__ __forceinline__ float bf_lo(uint32_t p) { return __uint_as_float(p << 16); }
__device__ __forceinline__ float bf_hi(uint32_t p) { return __uint_as_float(p & 0xFFFF0000u); }

__device__ __forceinline__ void mma_bf16(float* d, const uint32_t* a, uint32_t b0, uint32_t b1) {
    asm volatile(
        "mma.sync.aligned.m16n8k16.row.col.f32.bf16.bf16.f32 "
        "{%0,%1,%2,%3}, {%4,%5,%6,%7}, {%8,%9}, {%0,%1,%2,%3};"
        : "+f"(d[0]), "+f"(d[1]), "+f"(d[2]), "+f"(d[3])
        : "r"(a[0]), "r"(a[1]), "r"(a[2]), "r"(a[3]), "r"(b0), "r"(b1));
}

__global__ void __launch_bounds__(256, 1)
sage_hmma_kernel(const float4* __restrict__ agg, const int* __restrict__ deg,
                 const float4* __restrict__ X,
                 const uint16_t* __restrict__ bhi, const uint16_t* __restrict__ blo,
                 const float* __restrict__ bias, float4* __restrict__ out) {
    extern __shared__ char smem[];
    uint16_t* bhi_s = (uint16_t*)smem;                       // 67584 B
    uint16_t* blo_s = (uint16_t*)(smem + BELEMS * 2);        // 67584 B
    float*    bias_s = (float*)(smem + BELEMS * 4);          // 512 B

    const int tid = threadIdx.x;
    const int lane = tid & 31;
    const int warp = tid >> 5;

    // stage B hi/lo + bias
    {
        const uint4* s1 = (const uint4*)bhi;
        const uint4* s2 = (const uint4*)blo;
        uint4* d1 = (uint4*)bhi_s;
        uint4* d2 = (uint4*)blo_s;
        const int n16 = BELEMS * 2 / 16;   // 4224
        for (int i = tid; i < n16; i += 256) { d1[i] = s1[i]; d2[i] = s2[i]; }
        if (tid < 32) ((float4*)bias_s)[tid] = ((const float4*)bias)[tid];
    }
    __syncthreads();

    const int gid = lane >> 2;     // 0..7 (row within 8-group / n within tile)
    const int tig = lane & 3;      // 0..3 (k pair selector)

    const int row_base = blockIdx.x * 128 + warp * 16;
    const int r0 = row_base + gid;
    const int r1 = r0 + 8;
    const bool v0 = r0 < N_NODES;
    const bool v1 = r1 < N_NODES;
    const int rr0 = v0 ? r0 : 0;
    const int rr1 = v1 ? r1 : 0;

    int d0g = deg[rr0], d1g = deg[rr1];
    const float invd0 = 1.0f / (float)(d0g > 0 ? d0g : 1);
    const float invd1 = 1.0f / (float)(d1g > 0 ? d1g : 1);

    const float2* a0p = (const float2*)(agg + (size_t)rr0 * ROW4);
    const float2* a1p = (const float2*)(agg + (size_t)rr1 * ROW4);
    const float2* x0p = (const float2*)(X   + (size_t)rr0 * ROW4);
    const float2* x1p = (const float2*)(X   + (size_t)rr1 * ROW4);

    float acc[16][4];
#pragma unroll
    for (int j = 0; j < 16; ++j) {
        acc[j][0] = 0.f; acc[j][1] = 0.f; acc[j][2] = 0.f; acc[j][3] = 0.f;
    }

#pragma unroll 1
    for (int s = 0; s < 16; ++s) {
        // ---- build A fragments (hi + lo) for k-step s ----
        const bool is_mean = (s < 8);
        const int cb = (is_mean ? s : s - 8) * 8 + tig;   // float2 index in row
        float2 u00 = is_mean ? a0p[cb]     : x0p[cb];
        float2 u01 = is_mean ? a0p[cb + 4] : x0p[cb + 4];
        float2 u10 = is_mean ? a1p[cb]     : x1p[cb];
        float2 u11 = is_mean ? a1p[cb + 4] : x1p[cb + 4];
        if (is_mean) {
            u00.x *= invd0; u00.y *= invd0; u01.x *= invd0; u01.y *= invd0;
            u10.x *= invd1; u10.y *= invd1; u11.x *= invd1; u11.y *= invd1;
        }
        uint32_t ahi[4], alo[4];
        ahi[0] = pack_bf16x2(u00.x, u00.y);
        ahi[1] = pack_bf16x2(u10.x, u10.y);
        ahi[2] = pack_bf16x2(u01.x, u01.y);
        ahi[3] = pack_bf16x2(u11.x, u11.y);
        alo[0] = pack_bf16x2(u00.x - bf_lo(ahi[0]), u00.y - bf_hi(ahi[0]));
        alo[1] = pack_bf16x2(u10.x - bf_lo(ahi[1]), u10.y - bf_hi(ahi[1]));
        alo[2] = pack_bf16x2(u01.x - bf_lo(ahi[2]), u01.y - bf_hi(ahi[2]));
        alo[3] = pack_bf16x2(u11.x - bf_lo(ahi[3]), u11.y - bf_hi(ahi[3]));

        const int koff = s * 16 + tig * 2;
#pragma unroll
        for (int j = 0; j < 16; ++j) {
            const int n = j * 8 + gid;
            const uint16_t* ph = bhi_s + n * BSTRIDE + koff;
            const uint16_t* pl = blo_s + n * BSTRIDE + koff;
            uint32_t bh0 = *(const uint32_t*)ph;
            uint32_t bh1 = *(const uint32_t*)(ph + 8);
            uint32_t bl0 = *(const uint32_t*)pl;
            uint32_t bl1 = *(const uint32_t*)(pl + 8);
            mma_bf16(acc[j], ahi, bh0, bh1);   // Ahi*Bhi
            mma_bf16(acc[j], alo, bh0, bh1);   // Alo*Bhi
            mma_bf16(acc[j], ahi, bl0, bl1);   // Ahi*Blo
        }
    }

    // ---- epilogue: bias + relu, float2 stores ----
    float2* out2 = (float2*)out;
#pragma unroll
    for (int j = 0; j < 16; ++j) {
        const int c = j * 8 + tig * 2;
        const float b0 = bias_s[c], b1 = bias_s[c + 1];
        if (v0) {
            float2 o;
            o.x = fmaxf(0.f, acc[j][0] + b0);
            o.y = fmaxf(0.f, acc[j][1] + b1);
            out2[(size_t)r0 * 64 + (c >> 1)] = o;
        }
        if (v1) {
            float2 o;
            o.x = fmaxf(0.f, acc[j][2] + b0);
            o.y = fmaxf(0.f, acc[j][3] + b1);
            out2[(size_t)r1 * 64 + (c >> 1)] = o;
        }
    }
}

// logits = h @ w_cls + b_cls
__global__ void cls_kernel(const float4* __restrict__ h,
                           const float* __restrict__ wc,
                           const float* __restrict__ bc,
                           float* __restrict__ out) {
    __shared__ float ws[CH * N_CLS];
    __shared__ float bsh[N_CLS];
    for (int i = threadIdx.x; i < CH * N_CLS; i += blockDim.x) ws[i] = wc[i];
    if (threadIdx.x < N_CLS) bsh[threadIdx.x] = bc[threadIdx.x];
    __syncthreads();

    int r = blockIdx.x * blockDim.x + threadIdx.x;
    if (r >= N_NODES) return;

    float a0 = bsh[0], a1 = bsh[1], a2 = bsh[2];
    const float4* row = h + (size_t)r * ROW4;
#pragma unroll 8
    for (int kg = 0; kg < 32; ++kg) {
        float4 hv = row[kg];
#pragma unroll
        for (int kk = 0; kk < 4; ++kk) {
            float hh = reinterpret_cast<const float*>(&hv)[kk];
            int k = kg * 4 + kk;
            a0 = fmaf(hh, ws[k * 3 + 0], a0);
            a1 = fmaf(hh, ws[k * 3 + 1], a1);
            a2 = fmaf(hh, ws[k * 3 + 2], a2);
        }
    }
    out[(size_t)r * 3 + 0] = a0;
    out[(size_t)r * 3 + 1] = a1;
    out[(size_t)r * 3 + 2] = a2;
}

// ---------------- launch -----------------------------------------------------
extern "C" void kernel_launch(void* const* d_in, const int* in_sizes, int n_in,
                              void* d_out, int out_size) {
    const float* x     = (const float*)d_in[0];
    const int*   ei    = (const int*)d_in[1];     // int32 (JAX x64 disabled)
    const float* w_l1  = (const float*)d_in[2];
    const float* b_l1  = (const float*)d_in[3];
    const float* w_r1  = (const float*)d_in[4];
    const float* w_l2  = (const float*)d_in[5];
    const float* b_l2  = (const float*)d_in[6];
    const float* w_r2  = (const float*)d_in[7];
    const float* w_cls = (const float*)d_in[8];
    const float* b_cls = (const float*)d_in[9];
    float*       out   = (float*)d_out;

    float4 *agg, *h1, *h2;
    int* deg;
    uint16_t *bhi, *blo;
    cudaGetSymbolAddress((void**)&agg, g_agg);
    cudaGetSymbolAddress((void**)&h1,  g_h1);
    cudaGetSymbolAddress((void**)&h2,  g_h2);
    cudaGetSymbolAddress((void**)&deg, g_deg);
    cudaGetSymbolAddress((void**)&bhi, g_bhi);
    cudaGetSymbolAddress((void**)&blo, g_blo);

    const float4* x4 = reinterpret_cast<const float4*>(x);

    const int MMA_SMEM = BELEMS * 4 + 512;   // 135168 + 512 = 135680 B
    cudaFuncSetAttribute(sage_hmma_kernel,
                         cudaFuncAttributeMaxDynamicSharedMemorySize, MMA_SMEM);

    const int ZERO_BLOCKS = 1184;
    const int SCAT_BLOCKS = N_EDGES / 8;
    const int DEG_BLOCKS  = (N_EDGES + 255) / 256;
    const int CLS_BLOCKS  = (N_NODES + 255) / 256;
    const int PREP_BLOCKS = (128 * 256 + 255) / 256;

    // weight prep (independent of graph data)
    prep_weights<<<PREP_BLOCKS, 256>>>(w_l1, w_r1, bhi,          blo);
    prep_weights<<<PREP_BLOCKS, 256>>>(w_l2, w_r2, bhi + BELEMS, blo + BELEMS);

    // ---- layer 1 ----
    zero_kernel<<<ZERO_BLOCKS, 256>>>(agg, deg, 1);
    deg_kernel<<<DEG_BLOCKS, 256>>>(ei, deg);
    scatter_kernel<<<SCAT_BLOCKS, 256>>>(ei, x4, agg);
    sage_hmma_kernel<<<NBLK, 256, MMA_SMEM>>>(agg, deg, x4, bhi, blo, b_l1, h1);

    // ---- layer 2 ----
    zero_kernel<<<ZERO_BLOCKS, 256>>>(agg, deg, 0);
    scatter_kernel<<<SCAT_BLOCKS, 256>>>(ei, h1, agg);
    sage_hmma_kernel<<<NBLK, 256, MMA_SMEM>>>(agg, deg, h1, bhi + BELEMS, blo + BELEMS, b_l2, h2);

    // ---- classifier ----
    cls_kernel<<<CLS_BLOCKS, 256>>>(h2, w_cls, b_cls, out);
}

// round 9
// speedup vs baseline: 2.6680x; 1.3619x over previous
#include <cuda_runtime.h>
#include <cuda_bf16.h>
#include <cstdint>

// Problem constants
#define N_NODES 100000
#define N_EDGES 1000000
#define CH      128
#define N_CLS   3
#define ROW4    (CH / 4)
#define NBLK    ((N_NODES + 127) / 128)   // 782
#define NSCAN   ((N_NODES + 511) / 512)   // 196 scan blocks

// B smem layout: [n=128][k=256] bf16, row stride 264 elements -> conflict-free
#define BSTRIDE 264
#define BELEMS  (128 * BSTRIDE)           // 33792 elements per matrix

// ---------------- scratch (static device globals; no allocation) ------------
__device__ float4   g_agg[(size_t)N_NODES * ROW4];   // mean-aggregated features
__device__ float4   g_h1 [(size_t)N_NODES * ROW4];
__device__ float4   g_h2 [(size_t)N_NODES * ROW4];
__device__ int      g_deg[N_NODES];
__device__ int      g_start[N_NODES];
__device__ int      g_cursor[N_NODES];
__device__ int      g_csr[N_EDGES];
__device__ int      g_bsum[NSCAN];
__device__ uint16_t g_bhi[2][BELEMS];
__device__ uint16_t g_blo[2][BELEMS];

// ---------------- CSR build --------------------------------------------------
__global__ void zero_deg_kernel(int* __restrict__ deg) {
    int i = blockIdx.x * blockDim.x + threadIdx.x;
    if (i < N_NODES) deg[i] = 0;
}

__global__ void deg_kernel(const int* __restrict__ ei, int* __restrict__ deg) {
    int e = blockIdx.x * blockDim.x + threadIdx.x;
    if (e < N_EDGES) {
        int d = __ldg(&ei[N_EDGES + e]);
        atomicAdd(&deg[d], 1);
    }
}

// per-block sums of deg (512 nodes per block)
__global__ void scan1_kernel(const int* __restrict__ deg, int* __restrict__ bsum) {
    __shared__ int sh[512];
    int tid = threadIdx.x;
    int i = blockIdx.x * 512 + tid;
    sh[tid] = (i < N_NODES) ? deg[i] : 0;
    __syncthreads();
    for (int o = 256; o > 0; o >>= 1) {
        if (tid < o) sh[tid] += sh[tid + o];
        __syncthreads();
    }
    if (tid == 0) bsum[blockIdx.x] = sh[0];
}

// exclusive scan of block sums (tiny, single thread)
__global__ void scan2_kernel(int* __restrict__ bsum) {
    int acc = 0;
    for (int i = 0; i < NSCAN; ++i) { int v = bsum[i]; bsum[i] = acc; acc += v; }
}

// per-node exclusive starts = intra-block exclusive scan + block offset
__global__ void scan3_kernel(const int* __restrict__ deg, const int* __restrict__ bsum,
                             int* __restrict__ start, int* __restrict__ cursor) {
    __shared__ int sh[512];
    int tid = threadIdx.x;
    int i = blockIdx.x * 512 + tid;
    int v = (i < N_NODES) ? deg[i] : 0;
    sh[tid] = v;
    __syncthreads();
    for (int o = 1; o < 512; o <<= 1) {
        int t = (tid >= o) ? sh[tid - o] : 0;
        __syncthreads();
        sh[tid] += t;
        __syncthreads();
    }
    if (i < N_NODES) {
        int excl = sh[tid] - v + bsum[blockIdx.x];
        start[i]  = excl;
        cursor[i] = excl;
    }
}

__global__ void fill_kernel(const int* __restrict__ ei, int* __restrict__ cursor,
                            int* __restrict__ csr) {
    int e = blockIdx.x * blockDim.x + threadIdx.x;
    if (e < N_EDGES) {
        int s = __ldg(&ei[e]);
        int d = __ldg(&ei[N_EDGES + e]);
        int slot = atomicAdd(&cursor[d], 1);
        csr[slot] = s;
    }
}

// ---------------- gather-mean aggregation (warp per node) --------------------
__global__ void gather_kernel(const int* __restrict__ start, const int* __restrict__ deg,
                              const int* __restrict__ csr, const float4* __restrict__ feat,
                              float4* __restrict__ agg) {
    int w    = (blockIdx.x * blockDim.x + threadIdx.x) >> 5;
    int lane = threadIdx.x & 31;
    if (w >= N_NODES) return;
    int st = start[w];
    int n  = deg[w];
    float4 acc = make_float4(0.f, 0.f, 0.f, 0.f);
    int i = 0;
    for (; i + 2 <= n; i += 2) {
        int s0 = __ldg(&csr[st + i]);
        int s1 = __ldg(&csr[st + i + 1]);
        float4 v0 = feat[(size_t)s0 * ROW4 + lane];
        float4 v1 = feat[(size_t)s1 * ROW4 + lane];
        acc.x += v0.x; acc.y += v0.y; acc.z += v0.z; acc.w += v0.w;
        acc.x += v1.x; acc.y += v1.y; acc.z += v1.z; acc.w += v1.w;
    }
    if (i < n) {
        int s0 = __ldg(&csr[st + i]);
        float4 v0 = feat[(size_t)s0 * ROW4 + lane];
        acc.x += v0.x; acc.y += v0.y; acc.z += v0.z; acc.w += v0.w;
    }
    float inv = 1.0f / (float)(n > 0 ? n : 1);
    acc.x *= inv; acc.y *= inv; acc.z *= inv; acc.w *= inv;
    agg[(size_t)w * ROW4 + lane] = acc;
}

// ---------------- weight prep: transpose + bf16 hi/lo split ------------------
__global__ void prep_weights(const float* __restrict__ Wl, const float* __restrict__ Wr,
                             uint16_t* __restrict__ bhi, uint16_t* __restrict__ blo) {
    int idx = blockIdx.x * blockDim.x + threadIdx.x;
    if (idx >= 128 * 256) return;
    int n = idx & 127;
    int k = idx >> 7;
    float w = (k < 128) ? Wl[k * 128 + n] : Wr[(k - 128) * 128 + n];
    __nv_bfloat16 h = __float2bfloat16(w);
    float hf = __bfloat162float(h);
    __nv_bfloat16 l = __float2bfloat16(w - hf);
    int e = n * BSTRIDE + k;
    bhi[e] = *reinterpret_cast<unsigned short*>(&h);
    blo[e] = *reinterpret_cast<unsigned short*>(&l);
}

// ---------------- HMMA dual-GEMM + bias + relu -------------------------------
// out[r,:] = relu( [mean(r) | x(r)] (K=256) @ B + bias ), 3-term bf16 split.
__device__ __forceinline__ uint32_t pack_bf16x2(float lo, float hi) {
    uint32_t r;
    asm("cvt.rn.bf16x2.f32 %0, %1, %2;" : "=r"(r) : "f"(hi), "f"(lo));
    return r;
}
__device__ __forceinline__ float bf_lo(uint32_t p) { return __uint_as_float(p << 16); }
__device__ __forceinline__ float bf_hi(uint32_t p) { return __uint_as_float(p & 0xFFFF0000u); }

__device__ __forceinline__ void mma_bf16(float* d, const uint32_t* a, uint32_t b0, uint32_t b1) {
    asm volatile(
        "mma.sync.aligned.m16n8k16.row.col.f32.bf16.bf16.f32 "
        "{%0,%1,%2,%3}, {%4,%5,%6,%7}, {%8,%9}, {%0,%1,%2,%3};"
        : "+f"(d[0]), "+f"(d[1]), "+f"(d[2]), "+f"(d[3])
        : "r"(a[0]), "r"(a[1]), "r"(a[2]), "r"(a[3]), "r"(b0), "r"(b1));
}

__global__ void __launch_bounds__(256, 1)
sage_hmma_kernel(const float4* __restrict__ mean, const float4* __restrict__ X,
                 const uint16_t* __restrict__ bhi, const uint16_t* __restrict__ blo,
                 const float* __restrict__ bias, float4* __restrict__ out) {
    extern __shared__ char smem[];
    uint16_t* bhi_s = (uint16_t*)smem;
    uint16_t* blo_s = (uint16_t*)(smem + BELEMS * 2);
    float*    bias_s = (float*)(smem + BELEMS * 4);

    const int tid = threadIdx.x;
    const int lane = tid & 31;
    const int warp = tid >> 5;

    {
        const uint4* s1 = (const uint4*)bhi;
        const uint4* s2 = (const uint4*)blo;
        uint4* d1 = (uint4*)bhi_s;
        uint4* d2 = (uint4*)blo_s;
        const int n16 = BELEMS * 2 / 16;
        for (int i = tid; i < n16; i += 256) { d1[i] = s1[i]; d2[i] = s2[i]; }
        if (tid < 32) ((float4*)bias_s)[tid] = ((const float4*)bias)[tid];
    }
    __syncthreads();

    const int gid = lane >> 2;
    const int tig = lane & 3;

    const int row_base = blockIdx.x * 128 + warp * 16;
    const int r0 = row_base + gid;
    const int r1 = r0 + 8;
    const bool v0 = r0 < N_NODES;
    const bool v1 = r1 < N_NODES;
    const int rr0 = v0 ? r0 : 0;
    const int rr1 = v1 ? r1 : 0;

    const float2* a0p = (const float2*)(mean + (size_t)rr0 * ROW4);
    const float2* a1p = (const float2*)(mean + (size_t)rr1 * ROW4);
    const float2* x0p = (const float2*)(X    + (size_t)rr0 * ROW4);
    const float2* x1p = (const float2*)(X    + (size_t)rr1 * ROW4);

    float acc[16][4];
#pragma unroll
    for (int j = 0; j < 16; ++j) {
        acc[j][0] = 0.f; acc[j][1] = 0.f; acc[j][2] = 0.f; acc[j][3] = 0.f;
    }

#pragma unroll 1
    for (int s = 0; s < 16; ++s) {
        const bool is_mean = (s < 8);
        const int cb = (is_mean ? s : s - 8) * 8 + tig;
        float2 u00 = is_mean ? a0p[cb]     : x0p[cb];
        float2 u01 = is_mean ? a0p[cb + 4] : x0p[cb + 4];
        float2 u10 = is_mean ? a1p[cb]     : x1p[cb];
        float2 u11 = is_mean ? a1p[cb + 4] : x1p[cb + 4];

        uint32_t ahi[4], alo[4];
        ahi[0] = pack_bf16x2(u00.x, u00.y);
        ahi[1] = pack_bf16x2(u10.x, u10.y);
        ahi[2] = pack_bf16x2(u01.x, u01.y);
        ahi[3] = pack_bf16x2(u11.x, u11.y);
        alo[0] = pack_bf16x2(u00.x - bf_lo(ahi[0]), u00.y - bf_hi(ahi[0]));
        alo[1] = pack_bf16x2(u10.x - bf_lo(ahi[1]), u10.y - bf_hi(ahi[1]));
        alo[2] = pack_bf16x2(u01.x - bf_lo(ahi[2]), u01.y - bf_hi(ahi[2]));
        alo[3] = pack_bf16x2(u11.x - bf_lo(ahi[3]), u11.y - bf_hi(ahi[3]));

        const int koff = s * 16 + tig * 2;
#pragma unroll
        for (int j = 0; j < 16; ++j) {
            const int n = j * 8 + gid;
            const uint16_t* ph = bhi_s + n * BSTRIDE + koff;
            const uint16_t* pl = blo_s + n * BSTRIDE + koff;
            uint32_t bh0 = *(const uint32_t*)ph;
            uint32_t bh1 = *(const uint32_t*)(ph + 8);
            uint32_t bl0 = *(const uint32_t*)pl;
            uint32_t bl1 = *(const uint32_t*)(pl + 8);
            mma_bf16(acc[j], ahi, bh0, bh1);
            mma_bf16(acc[j], alo, bh0, bh1);
            mma_bf16(acc[j], ahi, bl0, bl1);
        }
    }

    float2* out2 = (float2*)out;
#pragma unroll
    for (int j = 0; j < 16; ++j) {
        const int c = j * 8 + tig * 2;
        const float b0 = bias_s[c], b1 = bias_s[c + 1];
        if (v0) {
            float2 o;
            o.x = fmaxf(0.f, acc[j][0] + b0);
            o.y = fmaxf(0.f, acc[j][1] + b1);
            out2[(size_t)r0 * 64 + (c >> 1)] = o;
        }
        if (v1) {
            float2 o;
            o.x = fmaxf(0.f, acc[j][2] + b0);
            o.y = fmaxf(0.f, acc[j][3] + b1);
            out2[(size_t)r1 * 64 + (c >> 1)] = o;
        }
    }
}

// logits = h @ w_cls + b_cls
__global__ void cls_kernel(const float4* __restrict__ h,
                           const float* __restrict__ wc,
                           const float* __restrict__ bc,
                           float* __restrict__ out) {
    __shared__ float ws[CH * N_CLS];
    __shared__ float bsh[N_CLS];
    for (int i = threadIdx.x; i < CH * N_CLS; i += blockDim.x) ws[i] = wc[i];
    if (threadIdx.x < N_CLS) bsh[threadIdx.x] = bc[threadIdx.x];
    __syncthreads();

    int r = blockIdx.x * blockDim.x + threadIdx.x;
    if (r >= N_NODES) return;

    float a0 = bsh[0], a1 = bsh[1], a2 = bsh[2];
    const float4* row = h + (size_t)r * ROW4;
#pragma unroll 8
    for (int kg = 0; kg < 32; ++kg) {
        float4 hv = row[kg];
#pragma unroll
        for (int kk = 0; kk < 4; ++kk) {
            float hh = reinterpret_cast<const float*>(&hv)[kk];
            int k = kg * 4 + kk;
            a0 = fmaf(hh, ws[k * 3 + 0], a0);
            a1 = fmaf(hh, ws[k * 3 + 1], a1);
            a2 = fmaf(hh, ws[k * 3 + 2], a2);
        }
    }
    out[(size_t)r * 3 + 0] = a0;
    out[(size_t)r * 3 + 1] = a1;
    out[(size_t)r * 3 + 2] = a2;
}

// ---------------- launch -----------------------------------------------------
extern "C" void kernel_launch(void* const* d_in, const int* in_sizes, int n_in,
                              void* d_out, int out_size) {
    const float* x     = (const float*)d_in[0];
    const int*   ei    = (const int*)d_in[1];
    const float* w_l1  = (const float*)d_in[2];
    const float* b_l1  = (const float*)d_in[3];
    const float* w_r1  = (const float*)d_in[4];
    const float* w_l2  = (const float*)d_in[5];
    const float* b_l2  = (const float*)d_in[6];
    const float* w_r2  = (const float*)d_in[7];
    const float* w_cls = (const float*)d_in[8];
    const float* b_cls = (const float*)d_in[9];
    float*       out   = (float*)d_out;

    float4 *agg, *h1, *h2;
    int *deg, *start, *cursor, *csr, *bsum;
    uint16_t *bhi, *blo;
    cudaGetSymbolAddress((void**)&agg,    g_agg);
    cudaGetSymbolAddress((void**)&h1,     g_h1);
    cudaGetSymbolAddress((void**)&h2,     g_h2);
    cudaGetSymbolAddress((void**)&deg,    g_deg);
    cudaGetSymbolAddress((void**)&start,  g_start);
    cudaGetSymbolAddress((void**)&cursor, g_cursor);
    cudaGetSymbolAddress((void**)&csr,    g_csr);
    cudaGetSymbolAddress((void**)&bsum,   g_bsum);
    cudaGetSymbolAddress((void**)&bhi,    g_bhi);
    cudaGetSymbolAddress((void**)&blo,    g_blo);

    const float4* x4 = reinterpret_cast<const float4*>(x);

    const int MMA_SMEM = BELEMS * 4 + 512;
    cudaFuncSetAttribute(sage_hmma_kernel,
                         cudaFuncAttributeMaxDynamicSharedMemorySize, MMA_SMEM);

    const int EDGE_BLOCKS = (N_EDGES + 255) / 256;
    const int NODE_BLOCKS = (N_NODES + 255) / 256;
    const int GATH_BLOCKS = (N_NODES * 32 + 255) / 256;   // warp per node
    const int PREP_BLOCKS = (128 * 256 + 255) / 256;

    // ---- weight prep ----
    prep_weights<<<PREP_BLOCKS, 256>>>(w_l1, w_r1, bhi,          blo);
    prep_weights<<<PREP_BLOCKS, 256>>>(w_l2, w_r2, bhi + BELEMS, blo + BELEMS);

    // ---- CSR build (once; reused by both layers) ----
    zero_deg_kernel<<<NODE_BLOCKS, 256>>>(deg);
    deg_kernel<<<EDGE_BLOCKS, 256>>>(ei, deg);
    scan1_kernel<<<NSCAN, 512>>>(deg, bsum);
    scan2_kernel<<<1, 1>>>(bsum);
    scan3_kernel<<<NSCAN, 512>>>(deg, bsum, start, cursor);
    fill_kernel<<<EDGE_BLOCKS, 256>>>(ei, cursor, csr);

    // ---- layer 1 ----
    gather_kernel<<<GATH_BLOCKS, 256>>>(start, deg, csr, x4, agg);
    sage_hmma_kernel<<<NBLK, 256, MMA_SMEM>>>(agg, x4, bhi, blo, b_l1, h1);

    // ---- layer 2 ----
    gather_kernel<<<GATH_BLOCKS, 256>>>(start, deg, csr, h1, agg);
    sage_hmma_kernel<<<NBLK, 256, MMA_SMEM>>>(agg, h1, bhi + BELEMS, blo + BELEMS, b_l2, h2);

    // ---- classifier ----
    cls_kernel<<<NODE_BLOCKS, 256>>>(h2, w_cls, b_cls, out);
}

// round 15
// speedup vs baseline: 3.0698x; 1.1506x over previous
#include <cuda_runtime.h>
#include <cuda_bf16.h>
#include <cstdint>

// Problem constants
#define N_NODES 100000
#define N_EDGES 1000000
#define CH      128
#define N_CLS   3
#define ROW4    (CH / 4)
#define NBLK    ((N_NODES + 127) / 128)   // 782
#define NSCAN   ((N_NODES + 511) / 512)   // 196 scan blocks

// B smem layout: [n=128][k=256] bf16, row stride 264 elements -> conflict-free
#define BSTRIDE 264
#define BELEMS  (128 * BSTRIDE)           // 33792 elements per matrix

// ---------------- scratch (static device globals; no allocation) ------------
__device__ float4   g_agg[(size_t)N_NODES * ROW4];
__device__ float4   g_h1 [(size_t)N_NODES * ROW4];
__device__ int      g_deg[N_NODES];
__device__ int      g_start[N_NODES];
__device__ int      g_cursor[N_NODES];
__device__ int      g_csr[N_EDGES];
__device__ int      g_bsum[NSCAN];
__device__ uint16_t g_bhi[2][BELEMS];
__device__ uint16_t g_blo[2][BELEMS];

// ---------------- CSR build --------------------------------------------------
__global__ void zero_deg_kernel(int* __restrict__ deg) {
    int i = blockIdx.x * blockDim.x + threadIdx.x;
    if (i < N_NODES) deg[i] = 0;
}

__global__ void deg_kernel(const int* __restrict__ ei, int* __restrict__ deg) {
    int e = blockIdx.x * blockDim.x + threadIdx.x;
    if (e < N_EDGES) {
        int d = __ldg(&ei[N_EDGES + e]);
        atomicAdd(&deg[d], 1);
    }
}

__global__ void scan1_kernel(const int* __restrict__ deg, int* __restrict__ bsum) {
    __shared__ int sh[512];
    int tid = threadIdx.x;
    int i = blockIdx.x * 512 + tid;
    sh[tid] = (i < N_NODES) ? deg[i] : 0;
    __syncthreads();
    for (int o = 256; o > 0; o >>= 1) {
        if (tid < o) sh[tid] += sh[tid + o];
        __syncthreads();
    }
    if (tid == 0) bsum[blockIdx.x] = sh[0];
}

__global__ void scan2_kernel(int* __restrict__ bsum) {
    int acc = 0;
    for (int i = 0; i < NSCAN; ++i) { int v = bsum[i]; bsum[i] = acc; acc += v; }
}

__global__ void scan3_kernel(const int* __restrict__ deg, const int* __restrict__ bsum,
                             int* __restrict__ start, int* __restrict__ cursor) {
    __shared__ int sh[512];
    int tid = threadIdx.x;
    int i = blockIdx.x * 512 + tid;
    int v = (i < N_NODES) ? deg[i] : 0;
    sh[tid] = v;
    __syncthreads();
    for (int o = 1; o < 512; o <<= 1) {
        int t = (tid >= o) ? sh[tid - o] : 0;
        __syncthreads();
        sh[tid] += t;
        __syncthreads();
    }
    if (i < N_NODES) {
        int excl = sh[tid] - v + bsum[blockIdx.x];
        start[i]  = excl;
        cursor[i] = excl;
    }
}

__global__ void fill_kernel(const int* __restrict__ ei, int* __restrict__ cursor,
                            int* __restrict__ csr) {
    int e = blockIdx.x * blockDim.x + threadIdx.x;
    if (e < N_EDGES) {
        int s = __ldg(&ei[e]);
        int d = __ldg(&ei[N_EDGES + e]);
        int slot = atomicAdd(&cursor[d], 1);
        csr[slot] = s;
    }
}

// ---------------- gather-mean aggregation (warp per node) --------------------
__global__ void gather_kernel(const int* __restrict__ start, const int* __restrict__ deg,
                              const int* __restrict__ csr, const float4* __restrict__ feat,
                              float4* __restrict__ agg) {
    int w    = (blockIdx.x * blockDim.x + threadIdx.x) >> 5;
    int lane = threadIdx.x & 31;
    if (w >= N_NODES) return;
    int st = start[w];
    int n  = deg[w];
    float4 acc = make_float4(0.f, 0.f, 0.f, 0.f);
    int i = 0;
    for (; i + 2 <= n; i += 2) {
        int s0 = __ldg(&csr[st + i]);
        int s1 = __ldg(&csr[st + i + 1]);
        float4 v0 = feat[(size_t)s0 * ROW4 + lane];
        float4 v1 = feat[(size_t)s1 * ROW4 + lane];
        acc.x += v0.x; acc.y += v0.y; acc.z += v0.z; acc.w += v0.w;
        acc.x += v1.x; acc.y += v1.y; acc.z += v1.z; acc.w += v1.w;
    }
    if (i < n) {
        int s0 = __ldg(&csr[st + i]);
        float4 v0 = feat[(size_t)s0 * ROW4 + lane];
        acc.x += v0.x; acc.y += v0.y; acc.z += v0.z; acc.w += v0.w;
    }
    float inv = 1.0f / (float)(n > 0 ? n : 1);
    acc.x *= inv; acc.y *= inv; acc.z *= inv; acc.w *= inv;
    agg[(size_t)w * ROW4 + lane] = acc;
}

// ---------------- weight prep: transpose + bf16 hi/lo split ------------------
__global__ void prep_weights(const float* __restrict__ Wl, const float* __restrict__ Wr,
                             uint16_t* __restrict__ bhi, uint16_t* __restrict__ blo) {
    int idx = blockIdx.x * blockDim.x + threadIdx.x;
    if (idx >= 128 * 256) return;
    int n = idx & 127;
    int k = idx >> 7;
    float w = (k < 128) ? Wl[k * 128 + n] : Wr[(k - 128) * 128 + n];
    __nv_bfloat16 h = __float2bfloat16(w);
    float hf = __bfloat162float(h);
    __nv_bfloat16 l = __float2bfloat16(w - hf);
    int e = n * BSTRIDE + k;
    bhi[e] = *reinterpret_cast<unsigned short*>(&h);
    blo[e] = *reinterpret_cast<unsigned short*>(&l);
}

// ---------------- HMMA dual-GEMM + bias + relu (+ fused classifier) ----------
__device__ __forceinline__ uint32_t pack_bf16x2(float lo, float hi) {
    uint32_t r;
    asm("cvt.rn.bf16x2.f32 %0, %1, %2;" : "=r"(r) : "f"(hi), "f"(lo));
    return r;
}
__device__ __forceinline__ float bf_lo(uint32_t p) { return __uint_as_float(p << 16); }
__device__ __forceinline__ float bf_hi(uint32_t p) { return __uint_as_float(p & 0xFFFF0000u); }

__device__ __forceinline__ void mma_bf16(float* d, const uint32_t* a, uint32_t b0, uint32_t b1) {
    asm volatile(
        "mma.sync.aligned.m16n8k16.row.col.f32.bf16.bf16.f32 "
        "{%0,%1,%2,%3}, {%4,%5,%6,%7}, {%8,%9}, {%0,%1,%2,%3};"
        : "+f"(d[0]), "+f"(d[1]), "+f"(d[2]), "+f"(d[3])
        : "r"(a[0]), "r"(a[1]), "r"(a[2]), "r"(a[3]), "r"(b0), "r"(b1));
}

template <bool FUSE_CLS>
__global__ void __launch_bounds__(256, 1)
sage_hmma_kernel(const float4* __restrict__ mean, const float4* __restrict__ X,
                 const uint16_t* __restrict__ bhi, const uint16_t* __restrict__ blo,
                 const float* __restrict__ bias, float4* __restrict__ out,
                 const float* __restrict__ wc, const float* __restrict__ bc,
                 float* __restrict__ cls_out) {
    extern __shared__ char smem[];
    uint16_t* bhi_s  = (uint16_t*)smem;
    uint16_t* blo_s  = (uint16_t*)(smem + BELEMS * 2);
    float*    bias_s = (float*)(smem + BELEMS * 4);            // 128 floats
    float*    wc_s   = (float*)(smem + BELEMS * 4 + 512);      // 128*3 floats
    float*    bc_s   = (float*)(smem + BELEMS * 4 + 512 + 1536);

    const int tid = threadIdx.x;
    const int lane = tid & 31;
    const int warp = tid >> 5;

    {
        const uint4* s1 = (const uint4*)bhi;
        const uint4* s2 = (const uint4*)blo;
        uint4* d1 = (uint4*)bhi_s;
        uint4* d2 = (uint4*)blo_s;
        const int n16 = BELEMS * 2 / 16;
        for (int i = tid; i < n16; i += 256) { d1[i] = s1[i]; d2[i] = s2[i]; }
        if (tid < 32) ((float4*)bias_s)[tid] = ((const float4*)bias)[tid];
        if (FUSE_CLS) {
            if (tid < CH * N_CLS) wc_s[tid] = wc[tid];
            for (int i = tid + 256; i < CH * N_CLS; i += 256) wc_s[i] = wc[i];
            if (tid < N_CLS) bc_s[tid] = bc[tid];
        }
    }
    __syncthreads();

    const int gid = lane >> 2;
    const int tig = lane & 3;

    const int row_base = blockIdx.x * 128 + warp * 16;
    const int r0 = row_base + gid;
    const int r1 = r0 + 8;
    const bool v0 = r0 < N_NODES;
    const bool v1 = r1 < N_NODES;
    const int rr0 = v0 ? r0 : 0;
    const int rr1 = v1 ? r1 : 0;

    const float2* a0p = (const float2*)(mean + (size_t)rr0 * ROW4);
    const float2* a1p = (const float2*)(mean + (size_t)rr1 * ROW4);
    const float2* x0p = (const float2*)(X    + (size_t)rr0 * ROW4);
    const float2* x1p = (const float2*)(X    + (size_t)rr1 * ROW4);

    float acc[16][4];
#pragma unroll
    for (int j = 0; j < 16; ++j) {
        acc[j][0] = 0.f; acc[j][1] = 0.f; acc[j][2] = 0.f; acc[j][3] = 0.f;
    }

    // ---- software-pipelined mainloop: prefetch A for s+1 before MMAs of s ----
    float2 c00, c01, c10, c11;
    {
        const int cb = tig;              // s = 0 (mean half)
        c00 = a0p[cb]; c01 = a0p[cb + 4];
        c10 = a1p[cb]; c11 = a1p[cb + 4];
    }

#pragma unroll 1
    for (int s = 0; s < 16; ++s) {
        float2 n00, n01, n10, n11;
        if (s < 15) {
            const int sn = s + 1;
            const bool nm = (sn < 8);
            const int cb = (nm ? sn : sn - 8) * 8 + tig;
            n00 = nm ? a0p[cb]     : x0p[cb];
            n01 = nm ? a0p[cb + 4] : x0p[cb + 4];
            n10 = nm ? a1p[cb]     : x1p[cb];
            n11 = nm ? a1p[cb + 4] : x1p[cb + 4];
        }

        uint32_t ahi[4], alo[4];
        ahi[0] = pack_bf16x2(c00.x, c00.y);
        ahi[1] = pack_bf16x2(c10.x, c10.y);
        ahi[2] = pack_bf16x2(c01.x, c01.y);
        ahi[3] = pack_bf16x2(c11.x, c11.y);
        alo[0] = pack_bf16x2(c00.x - bf_lo(ahi[0]), c00.y - bf_hi(ahi[0]));
        alo[1] = pack_bf16x2(c10.x - bf_lo(ahi[1]), c10.y - bf_hi(ahi[1]));
        alo[2] = pack_bf16x2(c01.x - bf_lo(ahi[2]), c01.y - bf_hi(ahi[2]));
        alo[3] = pack_bf16x2(c11.x - bf_lo(ahi[3]), c11.y - bf_hi(ahi[3]));

        const int koff = s * 16 + tig * 2;
#pragma unroll
        for (int j = 0; j < 16; ++j) {
            const int n = j * 8 + gid;
            const uint16_t* ph = bhi_s + n * BSTRIDE + koff;
            const uint16_t* pl = blo_s + n * BSTRIDE + koff;
            uint32_t bh0 = *(const uint32_t*)ph;
            uint32_t bh1 = *(const uint32_t*)(ph + 8);
            uint32_t bl0 = *(const uint32_t*)pl;
            uint32_t bl1 = *(const uint32_t*)(pl + 8);
            mma_bf16(acc[j], ahi, bh0, bh1);
            mma_bf16(acc[j], alo, bh0, bh1);
            mma_bf16(acc[j], ahi, bl0, bl1);
        }
        c00 = n00; c01 = n01; c10 = n10; c11 = n11;
    }

    // ---- epilogue ----
    if (!FUSE_CLS) {
        float2* out2 = (float2*)out;
#pragma unroll
        for (int j = 0; j < 16; ++j) {
            const int c = j * 8 + tig * 2;
            const float b0 = bias_s[c], b1 = bias_s[c + 1];
            if (v0) {
                float2 o;
                o.x = fmaxf(0.f, acc[j][0] + b0);
                o.y = fmaxf(0.f, acc[j][1] + b1);
                out2[(size_t)r0 * 64 + (c >> 1)] = o;
            }
            if (v1) {
                float2 o;
                o.x = fmaxf(0.f, acc[j][2] + b0);
                o.y = fmaxf(0.f, acc[j][3] + b1);
                out2[(size_t)r1 * 64 + (c >> 1)] = o;
            }
        }
    } else {
        // logits = relu(acc + bias) @ w_cls + b_cls, reduced over tig lanes
        float l0[N_CLS] = {0.f, 0.f, 0.f};
        float l1[N_CLS] = {0.f, 0.f, 0.f};
#pragma unroll
        for (int j = 0; j < 16; ++j) {
            const int c = j * 8 + tig * 2;
            const float b0 = bias_s[c], b1 = bias_s[c + 1];
            float h00 = fmaxf(0.f, acc[j][0] + b0);
            float h01 = fmaxf(0.f, acc[j][1] + b1);
            float h10 = fmaxf(0.f, acc[j][2] + b0);
            float h11 = fmaxf(0.f, acc[j][3] + b1);
#pragma unroll
            for (int q = 0; q < N_CLS; ++q) {
                float w0 = wc_s[c * 3 + q];
                float w1 = wc_s[(c + 1) * 3 + q];
                l0[q] = fmaf(h00, w0, fmaf(h01, w1, l0[q]));
                l1[q] = fmaf(h10, w0, fmaf(h11, w1, l1[q]));
            }
        }
#pragma unroll
        for (int q = 0; q < N_CLS; ++q) {
            l0[q] += __shfl_xor_sync(0xFFFFFFFF, l0[q], 1);
            l0[q] += __shfl_xor_sync(0xFFFFFFFF, l0[q], 2);
            l1[q] += __shfl_xor_sync(0xFFFFFFFF, l1[q], 1);
            l1[q] += __shfl_xor_sync(0xFFFFFFFF, l1[q], 2);
        }
        if (tig == 0) {
#pragma unroll
            for (int q = 0; q < N_CLS; ++q) {
                if (v0) cls_out[(size_t)r0 * 3 + q] = l0[q] + bc_s[q];
                if (v1) cls_out[(size_t)r1 * 3 + q] = l1[q] + bc_s[q];
            }
        }
    }
}

// ---------------- launch -----------------------------------------------------
extern "C" void kernel_launch(void* const* d_in, const int* in_sizes, int n_in,
                              void* d_out, int out_size) {
    const float* x     = (const float*)d_in[0];
    const int*   ei    = (const int*)d_in[1];
    const float* w_l1  = (const float*)d_in[2];
    const float* b_l1  = (const float*)d_in[3];
    const float* w_r1  = (const float*)d_in[4];
    const float* w_l2  = (const float*)d_in[5];
    const float* b_l2  = (const float*)d_in[6];
    const float* w_r2  = (const float*)d_in[7];
    const float* w_cls = (const float*)d_in[8];
    const float* b_cls = (const float*)d_in[9];
    float*       out   = (float*)d_out;

    float4 *agg, *h1;
    int *deg, *start, *cursor, *csr, *bsum;
    uint16_t *bhi, *blo;
    cudaGetSymbolAddress((void**)&agg,    g_agg);
    cudaGetSymbolAddress((void**)&h1,     g_h1);
    cudaGetSymbolAddress((void**)&deg,    g_deg);
    cudaGetSymbolAddress((void**)&start,  g_start);
    cudaGetSymbolAddress((void**)&cursor, g_cursor);
    cudaGetSymbolAddress((void**)&csr,    g_csr);
    cudaGetSymbolAddress((void**)&bsum,   g_bsum);
    cudaGetSymbolAddress((void**)&bhi,    g_bhi);
    cudaGetSymbolAddress((void**)&blo,    g_blo);

    const float4* x4 = reinterpret_cast<const float4*>(x);

    const int MMA_SMEM = BELEMS * 4 + 512 + 1536 + 16;   // B + bias + w_cls + b_cls
    cudaFuncSetAttribute(sage_hmma_kernel<false>,
                         cudaFuncAttributeMaxDynamicSharedMemorySize, MMA_SMEM);
    cudaFuncSetAttribute(sage_hmma_kernel<true>,
                         cudaFuncAttributeMaxDynamicSharedMemorySize, MMA_SMEM);

    const int EDGE_BLOCKS = (N_EDGES + 255) / 256;
    const int NODE_BLOCKS = (N_NODES + 255) / 256;
    const int GATH_BLOCKS = (N_NODES * 32 + 255) / 256;
    const int PREP_BLOCKS = (128 * 256 + 255) / 256;

    // ---- weight prep ----
    prep_weights<<<PREP_BLOCKS, 256>>>(w_l1, w_r1, bhi,          blo);
    prep_weights<<<PREP_BLOCKS, 256>>>(w_l2, w_r2, bhi + BELEMS, blo + BELEMS);

    // ---- CSR build ----
    zero_deg_kernel<<<NODE_BLOCKS, 256>>>(deg);
    deg_kernel<<<EDGE_BLOCKS, 256>>>(ei, deg);
    scan1_kernel<<<NSCAN, 512>>>(deg, bsum);
    scan2_kernel<<<1, 1>>>(bsum);
    scan3_kernel<<<NSCAN, 512>>>(deg, bsum, start, cursor);
    fill_kernel<<<EDGE_BLOCKS, 256>>>(ei, cursor, csr);

    // ---- layer 1 ----
    gather_kernel<<<GATH_BLOCKS, 256>>>(start, deg, csr, x4, agg);
    sage_hmma_kernel<false><<<NBLK, 256, MMA_SMEM>>>(agg, x4, bhi, blo, b_l1, h1,
                                                     nullptr, nullptr, nullptr);

    // ---- layer 2 + fused classifier ----
    gather_kernel<<<GATH_BLOCKS, 256>>>(start, deg, csr, h1, agg);
    sage_hmma_kernel<true><<<NBLK, 256, MMA_SMEM>>>(agg, h1, bhi + BELEMS, blo + BELEMS,
                                                    b_l2, nullptr, w_cls, b_cls, out);
}